// round 8
// baseline (speedup 1.0000x reference)
#include <cuda_runtime.h>
#include <cuda_bf16.h>
#include <cstdint>

#define CC   64
#define CINN 66
#define LL   40960
#define WW   256
#define TP   128
#define NTHR 256
#define NINST 32
#define NPARAMS 8513

#define OFF_W0 0
#define OFF_W1 4224
#define OFF_W2 8320
#define OFF_B0 8384
#define OFF_B1 8448
#define OFF_B2 8512
#define MASK_BIAS_SHIFT 2.19f

#define K1  80     // layer-1 K padded (66 -> 80, 5 k-steps)
#define KS1 88     // element stride (pad: 88*2B=176B, conflict-free frag loads)
#define KS2 72     // layer-2 element stride (64 + 8 pad)

// ---- smem byte offsets ----
#define W0H_O 0          // 64*88*2 = 11264
#define W0L_O 11264
#define W1H_O 22528      // 64*72*2 = 9216
#define W1L_O 31744
#define XH_O  40960      // 128*88*2 = 22528
#define XL_O  63488
#define HH_O  40960      // aliases X (X dead after layer-1 mma)
#define HL_O  59392      // 40960 + 128*72*2
#define RED_O 0          // 128*73*4 = 37376, aliases W0/W1 (dead after layer-2 mma)
#define MISC_O 86016
#define SMEM_TOTAL (MISC_O + (64*3 + 4) * 4)

__device__ __forceinline__ void bsplit(float v, uint16_t* hi, uint16_t* lo) {
    __nv_bfloat16 bh = __float2bfloat16(v);
    float r = v - __bfloat162float(bh);
    __nv_bfloat16 bl = __float2bfloat16(r);
    *hi = *(uint16_t*)&bh;
    *lo = *(uint16_t*)&bl;
}
__device__ __forceinline__ uint32_t ld32(const uint16_t* p) {
    return *(const uint32_t*)p;
}
__device__ __forceinline__ void mma16816(float* c,
                                         uint32_t a0, uint32_t a1, uint32_t a2, uint32_t a3,
                                         uint32_t b0, uint32_t b1) {
    asm volatile(
        "mma.sync.aligned.m16n8k16.row.col.f32.bf16.bf16.f32 "
        "{%0,%1,%2,%3}, {%4,%5,%6,%7}, {%8,%9}, {%0,%1,%2,%3};"
        : "+f"(c[0]), "+f"(c[1]), "+f"(c[2]), "+f"(c[3])
        : "r"(a0), "r"(a1), "r"(a2), "r"(a3), "r"(b0), "r"(b1));
}

extern __shared__ __align__(16) char smem[];

__global__ __launch_bounds__(NTHR, 2)
void condlane_mma_kernel(const float* __restrict__ x,
                         const float* __restrict__ params,
                         float* __restrict__ out)
{
    uint16_t* w0h = (uint16_t*)(smem + W0H_O);
    uint16_t* w0l = (uint16_t*)(smem + W0L_O);
    uint16_t* w1h = (uint16_t*)(smem + W1H_O);
    uint16_t* w1l = (uint16_t*)(smem + W1L_O);
    uint16_t* xh  = (uint16_t*)(smem + XH_O);
    uint16_t* xl  = (uint16_t*)(smem + XL_O);
    uint16_t* hh  = (uint16_t*)(smem + HH_O);
    uint16_t* hl  = (uint16_t*)(smem + HL_O);
    float*    sRed = (float*)(smem + RED_O);
    float*    sb0 = (float*)(smem + MISC_O);
    float*    sb1 = sb0 + 64;
    float*    sw2 = sb0 + 128;
    float*    sb2 = sb0 + 192;

    const int bx   = blockIdx.x;          // 0..319 pixel tile
    const int inst = blockIdx.y;          // 0..31
    const int img  = inst >> 3;
    const int tid  = threadIdx.x;
    const int wid  = tid >> 5;
    const int lane = tid & 31;
    const int l0   = bx * TP;

    const float* p = params + (size_t)inst * NPARAMS;

    // ---- stage W0 (bf16 hi/lo, k-padded to 80) ----
    for (int idx = tid; idx < 64 * K1; idx += NTHR) {
        int m = idx / K1, k = idx - m * K1;
        float v = (k < CINN) ? p[OFF_W0 + m * CINN + k] : 0.f;
        bsplit(v, &w0h[m * KS1 + k], &w0l[m * KS1 + k]);
    }
    // ---- stage W1 ----
    for (int idx = tid; idx < 64 * 64; idx += NTHR) {
        int m = idx >> 6, k = idx & 63;
        float v = p[OFF_W1 + m * 64 + k];
        bsplit(v, &w1h[m * KS2 + k], &w1l[m * KS2 + k]);
    }
    if (tid < 64) {
        sb0[tid] = p[OFF_B0 + tid];
        sb1[tid] = p[OFF_B1 + tid];
        sw2[tid] = p[OFF_W2 + tid];
    }
    if (tid == 0) sb2[0] = p[OFF_B2] - MASK_BIAS_SHIFT;

    // ---- stage X as [px][k] bf16 hi/lo (k 0,1 = coords; 66..79 zero) ----
    {
        const float yc  = (float)(l0 >> 8);
        const float xc0 = (float)(l0 & (WW - 1));
        const float* xb = x + (size_t)img * CC * LL + l0;
        for (int idx = tid; idx < K1 * TP; idx += NTHR) {
            int k = idx >> 7, px = idx & 127;   // consecutive tid -> consecutive px (coalesced)
            float v;
            if (k >= 2 && k < CINN)      v = xb[(size_t)(k - 2) * LL + px];
            else if (k == 0)             v = xc0 + (float)px;
            else if (k == 1)             v = yc;
            else                         v = 0.f;
            bsplit(v, &xh[px * KS1 + k], &xl[px * KS1 + k]);
        }
    }
    __syncthreads();

    // ---- warp tiling: 4 m-tiles x 16 n-tiles; warp = (m-tile, px-half) ----
    const int mt = wid & 3;          // rows mt*16..+15
    const int nh = wid >> 2;         // n-tiles nh*8..+7 (px nh*64..+63)
    const int g  = lane >> 2;        // group id
    const int t  = lane & 3;         // thread in group
    const int arow = mt * 16 + g;

    float acc[8][4];
    #pragma unroll
    for (int i = 0; i < 8; i++)
        #pragma unroll
        for (int j = 0; j < 4; j++) acc[i][j] = 0.f;

    // ======== layer 1: C1 = W0 @ X, K=80, 3 split passes ========
    {
        const uint16_t* pA[3] = {w0h, w0l, w0h};
        const uint16_t* pB[3] = {xh,  xh,  xl};
        #pragma unroll
        for (int ps = 0; ps < 3; ps++) {
            const uint16_t* A = pA[ps];
            const uint16_t* B = pB[ps];
            #pragma unroll
            for (int ks = 0; ks < 5; ks++) {
                int kb = ks * 16 + t * 2;
                uint32_t a0 = ld32(A + arow * KS1 + kb);
                uint32_t a1 = ld32(A + (arow + 8) * KS1 + kb);
                uint32_t a2 = ld32(A + arow * KS1 + kb + 8);
                uint32_t a3 = ld32(A + (arow + 8) * KS1 + kb + 8);
                #pragma unroll
                for (int nt = 0; nt < 8; nt++) {
                    int px = (nh * 8 + nt) * 8 + g;
                    uint32_t b0 = ld32(B + px * KS1 + kb);
                    uint32_t b1 = ld32(B + px * KS1 + kb + 8);
                    mma16816(acc[nt], a0, a1, a2, a3, b0, b1);
                }
            }
        }
    }
    __syncthreads();   // all reads of X done before H overwrites it

    // ---- epilogue 1: relu(C1 + b0) -> H [px][ch] bf16 hi/lo ----
    #pragma unroll
    for (int nt = 0; nt < 8; nt++) {
        int px0 = (nh * 8 + nt) * 8 + t * 2;
        int r0  = arow;
        float v00 = acc[nt][0] + sb0[r0];     v00 = v00 > 0.f ? v00 : 0.f;
        float v01 = acc[nt][1] + sb0[r0];     v01 = v01 > 0.f ? v01 : 0.f;
        float v10 = acc[nt][2] + sb0[r0 + 8]; v10 = v10 > 0.f ? v10 : 0.f;
        float v11 = acc[nt][3] + sb0[r0 + 8]; v11 = v11 > 0.f ? v11 : 0.f;
        bsplit(v00, &hh[px0 * KS2 + r0],           &hl[px0 * KS2 + r0]);
        bsplit(v01, &hh[(px0 + 1) * KS2 + r0],     &hl[(px0 + 1) * KS2 + r0]);
        bsplit(v10, &hh[px0 * KS2 + r0 + 8],       &hl[px0 * KS2 + r0 + 8]);
        bsplit(v11, &hh[(px0 + 1) * KS2 + r0 + 8], &hl[(px0 + 1) * KS2 + r0 + 8]);
    }
    __syncthreads();

    // ======== layer 2: C2 = W1 @ H, K=64, 3 split passes ========
    #pragma unroll
    for (int i = 0; i < 8; i++)
        #pragma unroll
        for (int j = 0; j < 4; j++) acc[i][j] = 0.f;
    {
        const uint16_t* pA[3] = {w1h, w1l, w1h};
        const uint16_t* pB[3] = {hh,  hh,  hl};
        #pragma unroll
        for (int ps = 0; ps < 3; ps++) {
            const uint16_t* A = pA[ps];
            const uint16_t* B = pB[ps];
            #pragma unroll
            for (int ks = 0; ks < 4; ks++) {
                int kb = ks * 16 + t * 2;
                uint32_t a0 = ld32(A + arow * KS2 + kb);
                uint32_t a1 = ld32(A + (arow + 8) * KS2 + kb);
                uint32_t a2 = ld32(A + arow * KS2 + kb + 8);
                uint32_t a3 = ld32(A + (arow + 8) * KS2 + kb + 8);
                #pragma unroll
                for (int nt = 0; nt < 8; nt++) {
                    int px = (nh * 8 + nt) * 8 + g;
                    uint32_t b0 = ld32(B + px * KS2 + kb);
                    uint32_t b1 = ld32(B + px * KS2 + kb + 8);
                    mma16816(acc[nt], a0, a1, a2, a3, b0, b1);
                }
            }
        }
    }
    __syncthreads();   // all reads of W0/W1/H done before sRed overwrites W region

    // ---- epilogue 2: sRed[px][ch] = w2[ch] * relu(C2 + b1)  (stride 73) ----
    #pragma unroll
    for (int nt = 0; nt < 8; nt++) {
        int px0 = (nh * 8 + nt) * 8 + t * 2;
        int r0  = arow;
        float v00 = acc[nt][0] + sb1[r0];     v00 = v00 > 0.f ? v00 : 0.f;
        float v01 = acc[nt][1] + sb1[r0];     v01 = v01 > 0.f ? v01 : 0.f;
        float v10 = acc[nt][2] + sb1[r0 + 8]; v10 = v10 > 0.f ? v10 : 0.f;
        float v11 = acc[nt][3] + sb1[r0 + 8]; v11 = v11 > 0.f ? v11 : 0.f;
        sRed[px0 * 73 + r0]           = sw2[r0] * v00;
        sRed[(px0 + 1) * 73 + r0]     = sw2[r0] * v01;
        sRed[px0 * 73 + r0 + 8]       = sw2[r0 + 8] * v10;
        sRed[(px0 + 1) * 73 + r0 + 8] = sw2[r0 + 8] * v11;
    }
    __syncthreads();

    // ======== layer 3: out[px] = b2 + sum_ch sRed[px][ch] ========
    if (tid < TP) {
        float s = sb2[0];
        const float* r = sRed + tid * 73;
        #pragma unroll
        for (int ch = 0; ch < 64; ch++) s += r[ch];
        out[(size_t)inst * LL + l0 + tid] = s;
    }
}

extern "C" void kernel_launch(void* const* d_in, const int* in_sizes, int n_in,
                              void* d_out, int out_size)
{
    const float* x      = (const float*)d_in[0];   // [4,64,160,256] fp32
    const float* params = (const float*)d_in[1];   // [32,8513] fp32
    float* out = (float*)d_out;                    // [1,32,160,256] fp32
    (void)in_sizes; (void)n_in; (void)out_size;

    cudaFuncSetAttribute(condlane_mma_kernel,
                         cudaFuncAttributeMaxDynamicSharedMemorySize, SMEM_TOTAL);

    dim3 grid(LL / TP, NINST);   // 320 x 32 = 10240 blocks
    condlane_mma_kernel<<<grid, NTHR, SMEM_TOTAL>>>(x, params, out);
}

// round 9
// speedup vs baseline: 1.1534x; 1.1534x over previous
#include <cuda_runtime.h>
#include <cuda_bf16.h>
#include <cstdint>

#define CC   64
#define CINN 66
#define LL   40960
#define WW   256
#define TP   128
#define NTHR 512
#define NINST 32
#define NPARAMS 8513

#define OFF_W0 0
#define OFF_W1 4224
#define OFF_W2 8320
#define OFF_B0 8384
#define OFF_B1 8448
#define OFF_B2 8512
#define MASK_BIAS_SHIFT 2.19f

#define K1  80     // layer-1 K padded (66 -> 80, 5 k-steps)
#define KS1 88     // element stride, 176B rows
#define KS2 72     // layer-2 element stride

// ---- precomputed bf16-split operands (device globals; allocation-free) ----
// gX: [img][px][KS1] hi and lo, px-major rows of 88 u16
__device__ __align__(16) uint16_t gXh[4 * LL * KS1];
__device__ __align__(16) uint16_t gXl[4 * LL * KS1];
// gW: per instance, flat image matching GEMM smem layout:
//   W0h (64*88) | W0l (64*88) | W1h (64*72) | W1l (64*72)  = 20480 u16
#define WIMG_U16 20480
__device__ __align__(16) uint16_t gW[NINST * WIMG_U16];

// ---- GEMM smem byte offsets (identical to verified R8 layout) ----
#define W0H_O 0
#define W0L_O 11264
#define W1H_O 22528
#define W1L_O 31744
#define XH_O  40960
#define XL_O  63488
#define HH_O  40960      // aliases X (X dead after layer-1 mma)
#define HL_O  59392
#define RED_O 0          // 128*73*4 = 37376, aliases W region (dead after layer-2 mma)
#define MISC_O 86016
#define SMEM_TOTAL (MISC_O + (64*3 + 4) * 4)

__device__ __forceinline__ void bsplit(float v, uint16_t* hi, uint16_t* lo) {
    __nv_bfloat16 bh = __float2bfloat16(v);
    float r = v - __bfloat162float(bh);
    __nv_bfloat16 bl = __float2bfloat16(r);
    *hi = *(uint16_t*)&bh;
    *lo = *(uint16_t*)&bl;
}
__device__ __forceinline__ uint32_t ld32(const uint16_t* p) {
    return *(const uint32_t*)p;
}
__device__ __forceinline__ void mma16816(float* c,
                                         uint32_t a0, uint32_t a1, uint32_t a2, uint32_t a3,
                                         uint32_t b0, uint32_t b1) {
    asm volatile(
        "mma.sync.aligned.m16n8k16.row.col.f32.bf16.bf16.f32 "
        "{%0,%1,%2,%3}, {%4,%5,%6,%7}, {%8,%9}, {%0,%1,%2,%3};"
        : "+f"(c[0]), "+f"(c[1]), "+f"(c[2]), "+f"(c[3])
        : "r"(a0), "r"(a1), "r"(a2), "r"(a3), "r"(b0), "r"(b1));
}

// ============ prep kernel 1: X -> bf16 hi/lo, [img][px][88] ============
__global__ __launch_bounds__(256)
void prep_x_kernel(const float* __restrict__ x)
{
    __shared__ __align__(16) float stage[TP * 89];   // [px][k] f32, stride 89 (conflict-free)
    const int tile = blockIdx.x & 511;               // 0..319 px tile (grid.x=320)
    const int img  = blockIdx.y;
    const int tid  = threadIdx.x;
    const int l0   = tile * TP;

    // phase 1: channels, coalesced global reads (px fast)
    const float* xb = x + (size_t)img * CC * LL + l0;
    for (int idx = tid; idx < CC * TP; idx += 256) {
        int ch = idx >> 7, px = idx & 127;
        stage[px * 89 + ch + 2] = xb[(size_t)ch * LL + px];
    }
    if (tid < TP) {
        stage[tid * 89 + 0] = (float)((l0 & (WW - 1)) + tid);  // x coord
        stage[tid * 89 + 1] = (float)(l0 >> 8);                // y coord
    }
    __syncthreads();

    // phase 2: split + write [px][k], k fast (coalesced 2B runs)
    for (int idx = tid; idx < TP * KS1; idx += 256) {
        int px = idx / KS1, k = idx - px * KS1;
        float v = (k < CINN) ? stage[px * 89 + k] : 0.f;
        size_t o = ((size_t)img * LL + l0 + px) * KS1 + k;
        bsplit(v, &gXh[o], &gXl[o]);
    }
}

// ============ prep kernel 2: weights -> bf16 hi/lo flat images ============
__global__ __launch_bounds__(256)
void prep_w_kernel(const float* __restrict__ params)
{
    const int inst = blockIdx.x;
    const int tid  = threadIdx.x;
    const float* p = params + (size_t)inst * NPARAMS;
    uint16_t* w = gW + (size_t)inst * WIMG_U16;

    for (int idx = tid; idx < 64 * KS1; idx += 256) {
        int m = idx / KS1, k = idx - m * KS1;
        float v = (k < CINN) ? p[OFF_W0 + m * CINN + k] : 0.f;
        bsplit(v, &w[idx], &w[5632 + idx]);
    }
    for (int idx = tid; idx < 64 * KS2; idx += 256) {
        int m = idx / KS2, k = idx - m * KS2;
        float v = (k < 64) ? p[OFF_W1 + m * 64 + k] : 0.f;
        bsplit(v, &w[11264 + idx], &w[11264 + 4608 + idx]);
    }
}

// ============ main GEMM kernel ============
extern __shared__ __align__(16) char smem[];

__global__ __launch_bounds__(NTHR, 2)
void condlane_mma_kernel(const float* __restrict__ params,
                         float* __restrict__ out)
{
    uint16_t* w0h = (uint16_t*)(smem + W0H_O);
    uint16_t* w0l = (uint16_t*)(smem + W0L_O);
    uint16_t* w1h = (uint16_t*)(smem + W1H_O);
    uint16_t* w1l = (uint16_t*)(smem + W1L_O);
    uint16_t* xh  = (uint16_t*)(smem + XH_O);
    uint16_t* xl  = (uint16_t*)(smem + XL_O);
    uint16_t* hh  = (uint16_t*)(smem + HH_O);
    uint16_t* hl  = (uint16_t*)(smem + HL_O);
    float*    sRed = (float*)(smem + RED_O);
    float*    sb0 = (float*)(smem + MISC_O);
    float*    sb1 = sb0 + 64;
    float*    sw2 = sb0 + 128;
    float*    sb2 = sb0 + 192;

    const int bx   = blockIdx.x;          // 0..319 pixel tile
    const int inst = blockIdx.y;          // 0..31
    const int img  = inst >> 3;
    const int tid  = threadIdx.x;
    const int wid  = tid >> 5;
    const int lane = tid & 31;
    const int l0   = bx * TP;

    // ---- flat copy-in: weights (2560 uint4) ----
    {
        const uint4* src = (const uint4*)(gW + (size_t)inst * WIMG_U16);
        uint4* dst = (uint4*)smem;
        for (int i = tid; i < 2560; i += NTHR) dst[i] = src[i];
    }
    // ---- flat copy-in: X hi/lo (1408 uint4 each) ----
    {
        const uint4* srch = (const uint4*)(gXh + ((size_t)img * LL + l0) * KS1);
        const uint4* srcl = (const uint4*)(gXl + ((size_t)img * LL + l0) * KS1);
        uint4* dh = (uint4*)(smem + XH_O);
        uint4* dl = (uint4*)(smem + XL_O);
        for (int i = tid; i < 1408; i += NTHR) { dh[i] = srch[i]; dl[i] = srcl[i]; }
    }
    {
        const float* p = params + (size_t)inst * NPARAMS;
        if (tid < 64) {
            sb0[tid] = p[OFF_B0 + tid];
            sb1[tid] = p[OFF_B1 + tid];
            sw2[tid] = p[OFF_W2 + tid];
        }
        if (tid == 0) sb2[0] = p[OFF_B2] - MASK_BIAS_SHIFT;
    }
    __syncthreads();

    // ---- warp tiling: 16 warps = (4 m-tiles) x (4 n-groups of 4 n-tiles) ----
    const int mt = wid & 3;          // rows mt*16..+15
    const int nh = wid >> 2;         // n-tiles nh*4..+3 (px nh*32..+31)
    const int g  = lane >> 2;
    const int t  = lane & 3;
    const int arow = mt * 16 + g;

    float acc[4][4];
    #pragma unroll
    for (int i = 0; i < 4; i++)
        #pragma unroll
        for (int j = 0; j < 4; j++) acc[i][j] = 0.f;

    // ======== layer 1: C1 = W0 @ X, K=80, 3 split passes ========
    {
        const uint16_t* pA[3] = {w0h, w0l, w0h};
        const uint16_t* pB[3] = {xh,  xh,  xl};
        #pragma unroll
        for (int ps = 0; ps < 3; ps++) {
            const uint16_t* A = pA[ps];
            const uint16_t* B = pB[ps];
            #pragma unroll
            for (int ks = 0; ks < 5; ks++) {
                int kb = ks * 16 + t * 2;
                uint32_t a0 = ld32(A + arow * KS1 + kb);
                uint32_t a1 = ld32(A + (arow + 8) * KS1 + kb);
                uint32_t a2 = ld32(A + arow * KS1 + kb + 8);
                uint32_t a3 = ld32(A + (arow + 8) * KS1 + kb + 8);
                #pragma unroll
                for (int nt = 0; nt < 4; nt++) {
                    int px = (nh * 4 + nt) * 8 + g;
                    uint32_t b0 = ld32(B + px * KS1 + kb);
                    uint32_t b1 = ld32(B + px * KS1 + kb + 8);
                    mma16816(acc[nt], a0, a1, a2, a3, b0, b1);
                }
            }
        }
    }
    __syncthreads();   // all reads of X done before H overwrites it

    // ---- epilogue 1: relu(C1 + b0) -> H [px][ch] bf16 hi/lo ----
    #pragma unroll
    for (int nt = 0; nt < 4; nt++) {
        int px0 = (nh * 4 + nt) * 8 + t * 2;
        int r0  = arow;
        float v00 = acc[nt][0] + sb0[r0];     v00 = v00 > 0.f ? v00 : 0.f;
        float v01 = acc[nt][1] + sb0[r0];     v01 = v01 > 0.f ? v01 : 0.f;
        float v10 = acc[nt][2] + sb0[r0 + 8]; v10 = v10 > 0.f ? v10 : 0.f;
        float v11 = acc[nt][3] + sb0[r0 + 8]; v11 = v11 > 0.f ? v11 : 0.f;
        bsplit(v00, &hh[px0 * KS2 + r0],           &hl[px0 * KS2 + r0]);
        bsplit(v01, &hh[(px0 + 1) * KS2 + r0],     &hl[(px0 + 1) * KS2 + r0]);
        bsplit(v10, &hh[px0 * KS2 + r0 + 8],       &hl[px0 * KS2 + r0 + 8]);
        bsplit(v11, &hh[(px0 + 1) * KS2 + r0 + 8], &hl[(px0 + 1) * KS2 + r0 + 8]);
    }
    __syncthreads();

    // ======== layer 2: C2 = W1 @ H, K=64, 3 split passes ========
    #pragma unroll
    for (int i = 0; i < 4; i++)
        #pragma unroll
        for (int j = 0; j < 4; j++) acc[i][j] = 0.f;
    {
        const uint16_t* pA[3] = {w1h, w1l, w1h};
        const uint16_t* pB[3] = {hh,  hh,  hl};
        #pragma unroll
        for (int ps = 0; ps < 3; ps++) {
            const uint16_t* A = pA[ps];
            const uint16_t* B = pB[ps];
            #pragma unroll
            for (int ks = 0; ks < 4; ks++) {
                int kb = ks * 16 + t * 2;
                uint32_t a0 = ld32(A + arow * KS2 + kb);
                uint32_t a1 = ld32(A + (arow + 8) * KS2 + kb);
                uint32_t a2 = ld32(A + arow * KS2 + kb + 8);
                uint32_t a3 = ld32(A + (arow + 8) * KS2 + kb + 8);
                #pragma unroll
                for (int nt = 0; nt < 4; nt++) {
                    int px = (nh * 4 + nt) * 8 + g;
                    uint32_t b0 = ld32(B + px * KS2 + kb);
                    uint32_t b1 = ld32(B + px * KS2 + kb + 8);
                    mma16816(acc[nt], a0, a1, a2, a3, b0, b1);
                }
            }
        }
    }
    __syncthreads();   // reads of W/H done before sRed overwrites W region

    // ---- epilogue 2: sRed[px][ch] = w2[ch] * relu(C2 + b1)  (stride 73) ----
    #pragma unroll
    for (int nt = 0; nt < 4; nt++) {
        int px0 = (nh * 4 + nt) * 8 + t * 2;
        int r0  = arow;
        float v00 = acc[nt][0] + sb1[r0];     v00 = v00 > 0.f ? v00 : 0.f;
        float v01 = acc[nt][1] + sb1[r0];     v01 = v01 > 0.f ? v01 : 0.f;
        float v10 = acc[nt][2] + sb1[r0 + 8]; v10 = v10 > 0.f ? v10 : 0.f;
        float v11 = acc[nt][3] + sb1[r0 + 8]; v11 = v11 > 0.f ? v11 : 0.f;
        sRed[px0 * 73 + r0]           = sw2[r0] * v00;
        sRed[(px0 + 1) * 73 + r0]     = sw2[r0] * v01;
        sRed[px0 * 73 + r0 + 8]       = sw2[r0 + 8] * v10;
        sRed[(px0 + 1) * 73 + r0 + 8] = sw2[r0 + 8] * v11;
    }
    __syncthreads();

    // ======== layer 3: out[px] = b2 + sum_ch sRed[px][ch] ========
    if (tid < TP) {
        float s = sb2[0];
        const float* r = sRed + tid * 73;
        #pragma unroll
        for (int ch = 0; ch < 64; ch++) s += r[ch];
        out[(size_t)inst * LL + l0 + tid] = s;
    }
}

extern "C" void kernel_launch(void* const* d_in, const int* in_sizes, int n_in,
                              void* d_out, int out_size)
{
    const float* x      = (const float*)d_in[0];   // [4,64,160,256] fp32
    const float* params = (const float*)d_in[1];   // [32,8513] fp32
    float* out = (float*)d_out;                    // [1,32,160,256] fp32
    (void)in_sizes; (void)n_in; (void)out_size;

    cudaFuncSetAttribute(condlane_mma_kernel,
                         cudaFuncAttributeMaxDynamicSharedMemorySize, SMEM_TOTAL);

    // prep: split X (per image) and weights (per instance) into bf16 hi/lo
    dim3 gx(LL / TP, 4);
    prep_x_kernel<<<gx, 256>>>(x);
    prep_w_kernel<<<NINST, 256>>>(params);

    dim3 grid(LL / TP, NINST);   // 320 x 32 = 10240 blocks
    condlane_mma_kernel<<<grid, NTHR, SMEM_TOTAL>>>(params, out);
}

// round 10
// speedup vs baseline: 1.4586x; 1.2646x over previous
#include <cuda_runtime.h>
#include <cuda_bf16.h>
#include <cstdint>

#define CC   64
#define CINN 66
#define LL   40960
#define WW   256
#define TP   128
#define NTHR 256
#define NINST 32
#define NPARAMS 8513

#define OFF_W0 0
#define OFF_W1 4224
#define OFF_W2 8320
#define OFF_B0 8384
#define OFF_B1 8448
#define OFF_B2 8512
#define MASK_BIAS_SHIFT 2.19f

#define K1  80     // layer-1 K padded (66 -> 80, 5 k-steps)
#define KS1 88     // element stride, 176B rows
#define KS2 72     // layer-2 element stride, 144B rows

// ---- precomputed bf16-split operands (device globals; allocation-free) ----
__device__ __align__(16) uint16_t gXh[4 * LL * KS1];
__device__ __align__(16) uint16_t gXl[4 * LL * KS1];
#define WIMG_U16 20480
__device__ __align__(16) uint16_t gW[NINST * WIMG_U16];

// ---- GEMM smem byte offsets ----
#define W0H_O 0
#define W0L_O 11264
#define W1H_O 22528
#define W1L_O 31744
#define XH_O  40960
#define XL_O  63488
#define HH_O  40960      // aliases X (X dead after layer-1 mma)
#define HL_O  59392
#define RED_O 0          // 128*73*4 = 37376, aliases W region (dead after layer-2 mma)
#define MISC_O 86016
#define SMEM_TOTAL (MISC_O + (64*3 + 4) * 4)

__device__ __forceinline__ void bsplit(float v, uint16_t* hi, uint16_t* lo) {
    __nv_bfloat16 bh = __float2bfloat16(v);
    float r = v - __bfloat162float(bh);
    __nv_bfloat16 bl = __float2bfloat16(r);
    *hi = *(uint16_t*)&bh;
    *lo = *(uint16_t*)&bl;
}
__device__ __forceinline__ uint32_t smem_u32(const void* p) {
    uint32_t a;
    asm("{ .reg .u64 t; cvta.to.shared.u64 t, %1; cvt.u32.u64 %0, t; }" : "=r"(a) : "l"(p));
    return a;
}
__device__ __forceinline__ void ldsm4(uint32_t* r, uint32_t addr) {
    asm volatile("ldmatrix.sync.aligned.m8n8.x4.shared.b16 {%0,%1,%2,%3}, [%4];"
                 : "=r"(r[0]), "=r"(r[1]), "=r"(r[2]), "=r"(r[3]) : "r"(addr));
}
__device__ __forceinline__ void mma16816(float* c, const uint32_t* a, uint32_t b0, uint32_t b1) {
    asm volatile(
        "mma.sync.aligned.m16n8k16.row.col.f32.bf16.bf16.f32 "
        "{%0,%1,%2,%3}, {%4,%5,%6,%7}, {%8,%9}, {%0,%1,%2,%3};"
        : "+f"(c[0]), "+f"(c[1]), "+f"(c[2]), "+f"(c[3])
        : "r"(a[0]), "r"(a[1]), "r"(a[2]), "r"(a[3]), "r"(b0), "r"(b1));
}

// ============ prep kernel 1: X -> bf16 hi/lo, [img][px][88] ============
__global__ __launch_bounds__(256)
void prep_x_kernel(const float* __restrict__ x)
{
    __shared__ __align__(16) float stage[TP * 89];
    const int tile = blockIdx.x;
    const int img  = blockIdx.y;
    const int tid  = threadIdx.x;
    const int l0   = tile * TP;

    const float* xb = x + (size_t)img * CC * LL + l0;
    for (int idx = tid; idx < CC * TP; idx += 256) {
        int ch = idx >> 7, px = idx & 127;
        stage[px * 89 + ch + 2] = xb[(size_t)ch * LL + px];
    }
    if (tid < TP) {
        stage[tid * 89 + 0] = (float)((l0 & (WW - 1)) + tid);
        stage[tid * 89 + 1] = (float)(l0 >> 8);
    }
    __syncthreads();

    for (int idx = tid; idx < TP * KS1; idx += 256) {
        int px = idx / KS1, k = idx - px * KS1;
        float v = (k < CINN) ? stage[px * 89 + k] : 0.f;
        size_t o = ((size_t)img * LL + l0 + px) * KS1 + k;
        bsplit(v, &gXh[o], &gXl[o]);
    }
}

// ============ prep kernel 2: weights -> bf16 hi/lo flat images ============
__global__ __launch_bounds__(256)
void prep_w_kernel(const float* __restrict__ params)
{
    const int inst = blockIdx.x;
    const int tid  = threadIdx.x;
    const float* p = params + (size_t)inst * NPARAMS;
    uint16_t* w = gW + (size_t)inst * WIMG_U16;

    for (int idx = tid; idx < 64 * KS1; idx += 256) {
        int m = idx / KS1, k = idx - m * KS1;
        float v = (k < CINN) ? p[OFF_W0 + m * CINN + k] : 0.f;
        bsplit(v, &w[idx], &w[5632 + idx]);
    }
    for (int idx = tid; idx < 64 * KS2; idx += 256) {
        int m = idx / KS2, k = idx - m * KS2;
        float v = (k < 64) ? p[OFF_W1 + m * 64 + k] : 0.f;
        bsplit(v, &w[11264 + idx], &w[11264 + 4608 + idx]);
    }
}

// ============ main GEMM kernel ============
extern __shared__ __align__(16) char smem[];

__global__ __launch_bounds__(NTHR, 2)
void condlane_mma_kernel(const float* __restrict__ params,
                         float* __restrict__ out)
{
    uint16_t* hh  = (uint16_t*)(smem + HH_O);
    uint16_t* hl  = (uint16_t*)(smem + HL_O);
    float*    sRed = (float*)(smem + RED_O);
    float*    sb0 = (float*)(smem + MISC_O);
    float*    sb1 = sb0 + 64;
    float*    sw2 = sb0 + 128;
    float*    sb2 = sb0 + 192;

    const int bx   = blockIdx.x;
    const int inst = blockIdx.y;
    const int img  = inst >> 3;
    const int tid  = threadIdx.x;
    const int wid  = tid >> 5;
    const int lane = tid & 31;
    const int l0   = bx * TP;
    const uint32_t sb = smem_u32(smem);

    // ---- flat copy-in: weights (2560 uint4), X hi/lo (1408 uint4 each) ----
    {
        const uint4* src = (const uint4*)(gW + (size_t)inst * WIMG_U16);
        uint4* dst = (uint4*)smem;
        for (int i = tid; i < 2560; i += NTHR) dst[i] = src[i];
        const uint4* srch = (const uint4*)(gXh + ((size_t)img * LL + l0) * KS1);
        const uint4* srcl = (const uint4*)(gXl + ((size_t)img * LL + l0) * KS1);
        uint4* dh = (uint4*)(smem + XH_O);
        uint4* dl = (uint4*)(smem + XL_O);
        for (int i = tid; i < 1408; i += NTHR) { dh[i] = srch[i]; dl[i] = srcl[i]; }
        const float* p = params + (size_t)inst * NPARAMS;
        if (tid < 64) {
            sb0[tid] = p[OFF_B0 + tid];
            sb1[tid] = p[OFF_B1 + tid];
            sw2[tid] = p[OFF_W2 + tid];
        }
        if (tid == 0) sb2[0] = p[OFF_B2] - MASK_BIAS_SHIFT;
    }
    __syncthreads();

    // ---- warp tiling: 8 warps = (2 m-halves) x (4 px-groups); 32 rows x 32 px each ----
    const int mh = wid & 1;          // rows mh*32 .. +31  (2 m-tiles of 16)
    const int ng = wid >> 1;         // px ng*32 .. +31    (4 n-tiles of 8)
    const int g  = lane >> 2;
    const int t  = lane & 3;

    // ldmatrix lane-address components
    const int aRow = (lane & 7) + ((lane >> 3) & 1) * 8;  // row within 16x16 A tile
    const int aCol = (lane >> 4) * 8;                     // k offset within tile
    const int bRow = (lane & 7) + (lane >> 4) * 8;        // px within 16-px B tile
    const int bCol = ((lane >> 3) & 1) * 8;               // k offset

    float acc[2][4][4];
    #pragma unroll
    for (int i = 0; i < 2; i++)
        #pragma unroll
        for (int j = 0; j < 4; j++)
            #pragma unroll
            for (int q = 0; q < 4; q++) acc[i][j][q] = 0.f;

    // ======== layer 1: K=80 (5 k-steps), reuse-ordered 3-pass split ========
    {
        uint32_t aH = sb + W0H_O + ((mh * 32 + aRow) * KS1 + aCol) * 2;
        uint32_t bH = sb + XH_O + ((ng * 32 + bRow) * KS1 + bCol) * 2;
        const uint32_t ALO = W0L_O - W0H_O;      // 11264
        const uint32_t BLO = XL_O - XH_O;        // 22528
        const uint32_t AMT = 16 * KS1 * 2;       // m-tile step
        const uint32_t BNT = 16 * KS1 * 2;       // 2-n-tile step
        #pragma unroll
        for (int ks = 0; ks < K1 / 16; ks++) {
            uint32_t kb = ks * 32;
            uint32_t ah[2][4], al[2][4], bh[2][4], bl[2][4];
            ldsm4(bh[0], bH + kb);
            ldsm4(bh[1], bH + BNT + kb);
            ldsm4(ah[0], aH + kb);
            ldsm4(ah[1], aH + AMT + kb);
            #pragma unroll
            for (int mt = 0; mt < 2; mt++)
                #pragma unroll
                for (int nt = 0; nt < 4; nt++)
                    mma16816(acc[mt][nt], ah[mt], bh[nt >> 1][(nt & 1) * 2], bh[nt >> 1][(nt & 1) * 2 + 1]);
            ldsm4(al[0], aH + ALO + kb);
            ldsm4(al[1], aH + ALO + AMT + kb);
            #pragma unroll
            for (int mt = 0; mt < 2; mt++)
                #pragma unroll
                for (int nt = 0; nt < 4; nt++)
                    mma16816(acc[mt][nt], al[mt], bh[nt >> 1][(nt & 1) * 2], bh[nt >> 1][(nt & 1) * 2 + 1]);
            ldsm4(bl[0], bH + BLO + kb);
            ldsm4(bl[1], bH + BLO + BNT + kb);
            #pragma unroll
            for (int mt = 0; mt < 2; mt++)
                #pragma unroll
                for (int nt = 0; nt < 4; nt++)
                    mma16816(acc[mt][nt], ah[mt], bl[nt >> 1][(nt & 1) * 2], bl[nt >> 1][(nt & 1) * 2 + 1]);
        }
    }
    __syncthreads();   // all reads of X done before H overwrites it

    // ---- epilogue 1: relu(C1 + b0) -> H [px][ch] bf16 hi/lo ----
    #pragma unroll
    for (int mt = 0; mt < 2; mt++)
        #pragma unroll
        for (int nt = 0; nt < 4; nt++) {
            int r0  = mh * 32 + mt * 16 + g;
            int px0 = ng * 32 + nt * 8 + t * 2;
            float v00 = acc[mt][nt][0] + sb0[r0];     v00 = v00 > 0.f ? v00 : 0.f;
            float v01 = acc[mt][nt][1] + sb0[r0];     v01 = v01 > 0.f ? v01 : 0.f;
            float v10 = acc[mt][nt][2] + sb0[r0 + 8]; v10 = v10 > 0.f ? v10 : 0.f;
            float v11 = acc[mt][nt][3] + sb0[r0 + 8]; v11 = v11 > 0.f ? v11 : 0.f;
            bsplit(v00, &hh[px0 * KS2 + r0],           &hl[px0 * KS2 + r0]);
            bsplit(v01, &hh[(px0 + 1) * KS2 + r0],     &hl[(px0 + 1) * KS2 + r0]);
            bsplit(v10, &hh[px0 * KS2 + r0 + 8],       &hl[px0 * KS2 + r0 + 8]);
            bsplit(v11, &hh[(px0 + 1) * KS2 + r0 + 8], &hl[(px0 + 1) * KS2 + r0 + 8]);
        }
    __syncthreads();

    // ======== layer 2: K=64 (4 k-steps) ========
    #pragma unroll
    for (int i = 0; i < 2; i++)
        #pragma unroll
        for (int j = 0; j < 4; j++)
            #pragma unroll
            for (int q = 0; q < 4; q++) acc[i][j][q] = 0.f;
    {
        uint32_t aH = sb + W1H_O + ((mh * 32 + aRow) * KS2 + aCol) * 2;
        uint32_t bH = sb + HH_O + ((ng * 32 + bRow) * KS2 + bCol) * 2;
        const uint32_t ALO = 9216;               // W1L_O - W1H_O
        const uint32_t BLO = HL_O - HH_O;        // 18432
        const uint32_t AMT = 16 * KS2 * 2;
        const uint32_t BNT = 16 * KS2 * 2;
        #pragma unroll
        for (int ks = 0; ks < 4; ks++) {
            uint32_t kb = ks * 32;
            uint32_t ah[2][4], al[2][4], bh[2][4], bl[2][4];
            ldsm4(bh[0], bH + kb);
            ldsm4(bh[1], bH + BNT + kb);
            ldsm4(ah[0], aH + kb);
            ldsm4(ah[1], aH + AMT + kb);
            #pragma unroll
            for (int mt = 0; mt < 2; mt++)
                #pragma unroll
                for (int nt = 0; nt < 4; nt++)
                    mma16816(acc[mt][nt], ah[mt], bh[nt >> 1][(nt & 1) * 2], bh[nt >> 1][(nt & 1) * 2 + 1]);
            ldsm4(al[0], aH + ALO + kb);
            ldsm4(al[1], aH + ALO + AMT + kb);
            #pragma unroll
            for (int mt = 0; mt < 2; mt++)
                #pragma unroll
                for (int nt = 0; nt < 4; nt++)
                    mma16816(acc[mt][nt], al[mt], bh[nt >> 1][(nt & 1) * 2], bh[nt >> 1][(nt & 1) * 2 + 1]);
            ldsm4(bl[0], bH + BLO + kb);
            ldsm4(bl[1], bH + BLO + BNT + kb);
            #pragma unroll
            for (int mt = 0; mt < 2; mt++)
                #pragma unroll
                for (int nt = 0; nt < 4; nt++)
                    mma16816(acc[mt][nt], ah[mt], bl[nt >> 1][(nt & 1) * 2], bl[nt >> 1][(nt & 1) * 2 + 1]);
        }
    }
    __syncthreads();   // reads of W/H done before sRed overwrites W region

    // ---- epilogue 2: sRed[px][ch] = w2[ch] * relu(C2 + b1)  (stride 73) ----
    #pragma unroll
    for (int mt = 0; mt < 2; mt++)
        #pragma unroll
        for (int nt = 0; nt < 4; nt++) {
            int r0  = mh * 32 + mt * 16 + g;
            int px0 = ng * 32 + nt * 8 + t * 2;
            float v00 = acc[mt][nt][0] + sb1[r0];     v00 = v00 > 0.f ? v00 : 0.f;
            float v01 = acc[mt][nt][1] + sb1[r0];     v01 = v01 > 0.f ? v01 : 0.f;
            float v10 = acc[mt][nt][2] + sb1[r0 + 8]; v10 = v10 > 0.f ? v10 : 0.f;
            float v11 = acc[mt][nt][3] + sb1[r0 + 8]; v11 = v11 > 0.f ? v11 : 0.f;
            sRed[px0 * 73 + r0]           = sw2[r0] * v00;
            sRed[(px0 + 1) * 73 + r0]     = sw2[r0] * v01;
            sRed[px0 * 73 + r0 + 8]       = sw2[r0 + 8] * v10;
            sRed[(px0 + 1) * 73 + r0 + 8] = sw2[r0 + 8] * v11;
        }
    __syncthreads();

    // ======== layer 3: out[px] = b2 + sum_ch sRed[px][ch] ========
    if (tid < TP) {
        float s = sb2[0];
        const float* r = sRed + tid * 73;
        #pragma unroll
        for (int ch = 0; ch < 64; ch++) s += r[ch];
        out[(size_t)inst * LL + l0 + tid] = s;
    }
}

extern "C" void kernel_launch(void* const* d_in, const int* in_sizes, int n_in,
                              void* d_out, int out_size)
{
    const float* x      = (const float*)d_in[0];
    const float* params = (const float*)d_in[1];
    float* out = (float*)d_out;
    (void)in_sizes; (void)n_in; (void)out_size;

    cudaFuncSetAttribute(condlane_mma_kernel,
                         cudaFuncAttributeMaxDynamicSharedMemorySize, SMEM_TOTAL);

    dim3 gx(LL / TP, 4);
    prep_x_kernel<<<gx, 256>>>(x);
    prep_w_kernel<<<NINST, 256>>>(params);

    dim3 grid(LL / TP, NINST);   // 320 x 32
    condlane_mma_kernel<<<grid, NTHR, SMEM_TOTAL>>>(params, out);
}

// round 11
// speedup vs baseline: 1.5964x; 1.0945x over previous
#include <cuda_runtime.h>
#include <cuda_bf16.h>
#include <cstdint>

#define CC   64
#define CINN 66
#define LL   40960
#define WW   256
#define TP   128
#define NTHR 256
#define NINST 32
#define NPARAMS 8513

#define OFF_W0 0
#define OFF_W1 4224
#define OFF_W2 8320
#define OFF_B0 8384
#define OFF_B1 8448
#define OFF_B2 8512
#define MASK_BIAS_SHIFT 2.19f

#define K1  80     // layer-1 K padded (66 -> 80, 5 k-steps)
#define KS1 80     // element stride, 160B rows (16B aligned, conflict-free)
#define KS2 72     // layer-2 element stride, 144B rows

// ---- precomputed bf16-split operands (device globals; allocation-free) ----
__device__ __align__(16) uint16_t gXh[4 * LL * KS1];
__device__ __align__(16) uint16_t gXl[4 * LL * KS1];
// per-instance flat weight image: W0h(5120) W0l(5120) W1h(4608) W1l(4608) u16
#define WIMG_U16 19456
__device__ __align__(16) uint16_t gW[NINST * WIMG_U16];

// ---- GEMM smem byte offsets ----
#define W0H_O 0
#define W0L_O 10240
#define W1H_O 20480
#define W1L_O 29696
#define XH_O  38912     // 128*80*2 = 20480
#define XL_O  59392
#define HH_O  38912     // aliases X (X dead after layer-1 mma), 128*72*2 = 18432
#define HL_O  57344
#define MISC_O 79872
#define SMEM_TOTAL (MISC_O + (64*3 + 4) * 4 + 256 * 4)   // biases/w2/b2 + sPart[256]

__device__ __forceinline__ void bsplit(float v, uint16_t* hi, uint16_t* lo) {
    __nv_bfloat16 bh = __float2bfloat16(v);
    float r = v - __bfloat162float(bh);
    __nv_bfloat16 bl = __float2bfloat16(r);
    *hi = *(uint16_t*)&bh;
    *lo = *(uint16_t*)&bl;
}
__device__ __forceinline__ uint32_t smem_u32(const void* p) {
    uint32_t a;
    asm("{ .reg .u64 t; cvta.to.shared.u64 t, %1; cvt.u32.u64 %0, t; }" : "=r"(a) : "l"(p));
    return a;
}
__device__ __forceinline__ void ldsm4(uint32_t* r, uint32_t addr) {
    asm volatile("ldmatrix.sync.aligned.m8n8.x4.shared.b16 {%0,%1,%2,%3}, [%4];"
                 : "=r"(r[0]), "=r"(r[1]), "=r"(r[2]), "=r"(r[3]) : "r"(addr));
}
__device__ __forceinline__ void mma16816(float* c, const uint32_t* a, uint32_t b0, uint32_t b1) {
    asm volatile(
        "mma.sync.aligned.m16n8k16.row.col.f32.bf16.bf16.f32 "
        "{%0,%1,%2,%3}, {%4,%5,%6,%7}, {%8,%9}, {%0,%1,%2,%3};"
        : "+f"(c[0]), "+f"(c[1]), "+f"(c[2]), "+f"(c[3])
        : "r"(a[0]), "r"(a[1]), "r"(a[2]), "r"(a[3]), "r"(b0), "r"(b1));
}

// ============ prep kernel 1: X -> bf16 hi/lo, [img][px][80] ============
__global__ __launch_bounds__(256)
void prep_x_kernel(const float* __restrict__ x)
{
    __shared__ __align__(16) float stage[TP * 89];
    const int tile = blockIdx.x;
    const int img  = blockIdx.y;
    const int tid  = threadIdx.x;
    const int l0   = tile * TP;

    const float* xb = x + (size_t)img * CC * LL + l0;
    for (int idx = tid; idx < CC * TP; idx += 256) {
        int ch = idx >> 7, px = idx & 127;
        stage[px * 89 + ch + 2] = xb[(size_t)ch * LL + px];
    }
    if (tid < TP) {
        stage[tid * 89 + 0] = (float)((l0 & (WW - 1)) + tid);
        stage[tid * 89 + 1] = (float)(l0 >> 8);
    }
    __syncthreads();

    for (int idx = tid; idx < TP * KS1; idx += 256) {
        int px = idx / KS1, k = idx - px * KS1;
        float v = (k < CINN) ? stage[px * 89 + k] : 0.f;
        size_t o = ((size_t)img * LL + l0 + px) * KS1 + k;
        bsplit(v, &gXh[o], &gXl[o]);
    }
}

// ============ prep kernel 2: weights -> bf16 hi/lo flat images ============
__global__ __launch_bounds__(256)
void prep_w_kernel(const float* __restrict__ params)
{
    const int inst = blockIdx.x;
    const int tid  = threadIdx.x;
    const float* p = params + (size_t)inst * NPARAMS;
    uint16_t* w = gW + (size_t)inst * WIMG_U16;

    for (int idx = tid; idx < 64 * KS1; idx += 256) {
        int m = idx / KS1, k = idx - m * KS1;
        float v = (k < CINN) ? p[OFF_W0 + m * CINN + k] : 0.f;
        bsplit(v, &w[idx], &w[5120 + idx]);
    }
    for (int idx = tid; idx < 64 * KS2; idx += 256) {
        int m = idx / KS2, k = idx - m * KS2;
        float v = (k < 64) ? p[OFF_W1 + m * 64 + k] : 0.f;
        bsplit(v, &w[10240 + idx], &w[14848 + idx]);
    }
}

// ============ main GEMM kernel ============
extern __shared__ __align__(16) char smem[];

__global__ __launch_bounds__(NTHR, 2)
void condlane_mma_kernel(const float* __restrict__ params,
                         float* __restrict__ out)
{
    uint16_t* hh  = (uint16_t*)(smem + HH_O);
    uint16_t* hl  = (uint16_t*)(smem + HL_O);
    float*    sb0 = (float*)(smem + MISC_O);
    float*    sb1 = sb0 + 64;
    float*    sw2 = sb0 + 128;
    float*    sb2 = sb0 + 192;
    float*    sPart = sb0 + 196;        // [2][128]

    const int bx   = blockIdx.x;
    const int inst = blockIdx.y;
    const int img  = inst >> 3;
    const int tid  = threadIdx.x;
    const int wid  = tid >> 5;
    const int lane = tid & 31;
    const int l0   = bx * TP;
    const uint32_t sb = smem_u32(smem);

    // ---- flat copy-in: weights (2432 uint4), X hi/lo (1280 uint4 each) ----
    {
        const uint4* src = (const uint4*)(gW + (size_t)inst * WIMG_U16);
        uint4* dst = (uint4*)smem;
        for (int i = tid; i < 2432; i += NTHR) dst[i] = src[i];
        const uint4* srch = (const uint4*)(gXh + ((size_t)img * LL + l0) * KS1);
        const uint4* srcl = (const uint4*)(gXl + ((size_t)img * LL + l0) * KS1);
        uint4* dh = (uint4*)(smem + XH_O);
        uint4* dl = (uint4*)(smem + XL_O);
        for (int i = tid; i < 1280; i += NTHR) { dh[i] = srch[i]; dl[i] = srcl[i]; }
        const float* p = params + (size_t)inst * NPARAMS;
        if (tid < 64) {
            sb0[tid] = p[OFF_B0 + tid];
            sb1[tid] = p[OFF_B1 + tid];
            sw2[tid] = p[OFF_W2 + tid];
        }
        if (tid == 0) sb2[0] = p[OFF_B2] - MASK_BIAS_SHIFT;
    }
    __syncthreads();

    // ---- warp tiling: 8 warps = (2 m-halves) x (4 px-groups); 32 rows x 32 px each ----
    const int mh = wid & 1;
    const int ng = wid >> 1;
    const int g  = lane >> 2;
    const int t  = lane & 3;

    const int aRow = (lane & 7) + ((lane >> 3) & 1) * 8;
    const int aCol = (lane >> 4) * 8;
    const int bRow = (lane & 7) + (lane >> 4) * 8;
    const int bCol = ((lane >> 3) & 1) * 8;

    float acc[2][4][4];
    #pragma unroll
    for (int i = 0; i < 2; i++)
        #pragma unroll
        for (int j = 0; j < 4; j++)
            #pragma unroll
            for (int q = 0; q < 4; q++) acc[i][j][q] = 0.f;

    // ======== layer 1: K=80 (5 k-steps), reuse-ordered 3-pass split ========
    {
        uint32_t aH = sb + W0H_O + ((mh * 32 + aRow) * KS1 + aCol) * 2;
        uint32_t bH = sb + XH_O + ((ng * 32 + bRow) * KS1 + bCol) * 2;
        const uint32_t ALO = W0L_O - W0H_O;      // 10240
        const uint32_t BLO = XL_O - XH_O;        // 20480
        const uint32_t AMT = 16 * KS1 * 2;       // 2560
        const uint32_t BNT = 16 * KS1 * 2;
        #pragma unroll
        for (int ks = 0; ks < K1 / 16; ks++) {
            uint32_t kb = ks * 32;
            uint32_t ah[2][4], al[2][4], bh[2][4], bl[2][4];
            ldsm4(bh[0], bH + kb);
            ldsm4(bh[1], bH + BNT + kb);
            ldsm4(ah[0], aH + kb);
            ldsm4(ah[1], aH + AMT + kb);
            #pragma unroll
            for (int mt = 0; mt < 2; mt++)
                #pragma unroll
                for (int nt = 0; nt < 4; nt++)
                    mma16816(acc[mt][nt], ah[mt], bh[nt >> 1][(nt & 1) * 2], bh[nt >> 1][(nt & 1) * 2 + 1]);
            ldsm4(al[0], aH + ALO + kb);
            ldsm4(al[1], aH + ALO + AMT + kb);
            #pragma unroll
            for (int mt = 0; mt < 2; mt++)
                #pragma unroll
                for (int nt = 0; nt < 4; nt++)
                    mma16816(acc[mt][nt], al[mt], bh[nt >> 1][(nt & 1) * 2], bh[nt >> 1][(nt & 1) * 2 + 1]);
            ldsm4(bl[0], bH + BLO + kb);
            ldsm4(bl[1], bH + BLO + BNT + kb);
            #pragma unroll
            for (int mt = 0; mt < 2; mt++)
                #pragma unroll
                for (int nt = 0; nt < 4; nt++)
                    mma16816(acc[mt][nt], ah[mt], bl[nt >> 1][(nt & 1) * 2], bl[nt >> 1][(nt & 1) * 2 + 1]);
        }
    }
    __syncthreads();   // all reads of X done before H overwrites it

    // ---- epilogue 1: relu(C1 + b0) -> H [px][ch] bf16 hi/lo ----
    #pragma unroll
    for (int mt = 0; mt < 2; mt++)
        #pragma unroll
        for (int nt = 0; nt < 4; nt++) {
            int r0  = mh * 32 + mt * 16 + g;
            int px0 = ng * 32 + nt * 8 + t * 2;
            float v00 = acc[mt][nt][0] + sb0[r0];     v00 = v00 > 0.f ? v00 : 0.f;
            float v01 = acc[mt][nt][1] + sb0[r0];     v01 = v01 > 0.f ? v01 : 0.f;
            float v10 = acc[mt][nt][2] + sb0[r0 + 8]; v10 = v10 > 0.f ? v10 : 0.f;
            float v11 = acc[mt][nt][3] + sb0[r0 + 8]; v11 = v11 > 0.f ? v11 : 0.f;
            bsplit(v00, &hh[px0 * KS2 + r0],           &hl[px0 * KS2 + r0]);
            bsplit(v01, &hh[(px0 + 1) * KS2 + r0],     &hl[(px0 + 1) * KS2 + r0]);
            bsplit(v10, &hh[px0 * KS2 + r0 + 8],       &hl[px0 * KS2 + r0 + 8]);
            bsplit(v11, &hh[(px0 + 1) * KS2 + r0 + 8], &hl[(px0 + 1) * KS2 + r0 + 8]);
        }
    __syncthreads();

    // ======== layer 2: K=64 (4 k-steps) ========
    #pragma unroll
    for (int i = 0; i < 2; i++)
        #pragma unroll
        for (int j = 0; j < 4; j++)
            #pragma unroll
            for (int q = 0; q < 4; q++) acc[i][j][q] = 0.f;
    {
        uint32_t aH = sb + W1H_O + ((mh * 32 + aRow) * KS2 + aCol) * 2;
        uint32_t bH = sb + HH_O + ((ng * 32 + bRow) * KS2 + bCol) * 2;
        const uint32_t ALO = W1L_O - W1H_O;      // 9216
        const uint32_t BLO = HL_O - HH_O;        // 18432
        const uint32_t AMT = 16 * KS2 * 2;       // 2304
        const uint32_t BNT = 16 * KS2 * 2;
        #pragma unroll
        for (int ks = 0; ks < 4; ks++) {
            uint32_t kb = ks * 32;
            uint32_t ah[2][4], al[2][4], bh[2][4], bl[2][4];
            ldsm4(bh[0], bH + kb);
            ldsm4(bh[1], bH + BNT + kb);
            ldsm4(ah[0], aH + kb);
            ldsm4(ah[1], aH + AMT + kb);
            #pragma unroll
            for (int mt = 0; mt < 2; mt++)
                #pragma unroll
                for (int nt = 0; nt < 4; nt++)
                    mma16816(acc[mt][nt], ah[mt], bh[nt >> 1][(nt & 1) * 2], bh[nt >> 1][(nt & 1) * 2 + 1]);
            ldsm4(al[0], aH + ALO + kb);
            ldsm4(al[1], aH + ALO + AMT + kb);
            #pragma unroll
            for (int mt = 0; mt < 2; mt++)
                #pragma unroll
                for (int nt = 0; nt < 4; nt++)
                    mma16816(acc[mt][nt], al[mt], bh[nt >> 1][(nt & 1) * 2], bh[nt >> 1][(nt & 1) * 2 + 1]);
            ldsm4(bl[0], bH + BLO + kb);
            ldsm4(bl[1], bH + BLO + BNT + kb);
            #pragma unroll
            for (int mt = 0; mt < 2; mt++)
                #pragma unroll
                for (int nt = 0; nt < 4; nt++)
                    mma16816(acc[mt][nt], ah[mt], bl[nt >> 1][(nt & 1) * 2], bl[nt >> 1][(nt & 1) * 2 + 1]);
        }
    }

    // ---- epilogue 2 + layer 3, all in registers: part[px] = sum_rows w2[r]*relu(C2+b1) ----
    float part[8];
    #pragma unroll
    for (int i = 0; i < 8; i++) part[i] = 0.f;
    #pragma unroll
    for (int mt = 0; mt < 2; mt++)
        #pragma unroll
        for (int nt = 0; nt < 4; nt++) {
            int r0 = mh * 32 + mt * 16 + g;
            float w2a = sw2[r0], w2b = sw2[r0 + 8];
            float v00 = acc[mt][nt][0] + sb1[r0];     v00 = v00 > 0.f ? v00 : 0.f;
            float v01 = acc[mt][nt][1] + sb1[r0];     v01 = v01 > 0.f ? v01 : 0.f;
            float v10 = acc[mt][nt][2] + sb1[r0 + 8]; v10 = v10 > 0.f ? v10 : 0.f;
            float v11 = acc[mt][nt][3] + sb1[r0 + 8]; v11 = v11 > 0.f ? v11 : 0.f;
            part[nt * 2]     += w2a * v00 + w2b * v10;
            part[nt * 2 + 1] += w2a * v01 + w2b * v11;
        }
    // fold the warp's 32 rows: butterfly over g (lane bits 2,3,4)
    #pragma unroll
    for (int i = 0; i < 8; i++) {
        part[i] += __shfl_xor_sync(0xffffffffu, part[i], 4);
        part[i] += __shfl_xor_sync(0xffffffffu, part[i], 8);
        part[i] += __shfl_xor_sync(0xffffffffu, part[i], 16);
    }
    if (g == 0) {   // lanes 0..3 hold the warp total
        #pragma unroll
        for (int nt = 0; nt < 4; nt++) {
            int px0 = ng * 32 + nt * 8 + t * 2;
            sPart[mh * 128 + px0]     = part[nt * 2];
            sPart[mh * 128 + px0 + 1] = part[nt * 2 + 1];
        }
    }
    __syncthreads();

    if (tid < TP) {
        out[(size_t)inst * LL + l0 + tid] = sb2[0] + sPart[tid] + sPart[128 + tid];
    }
}

extern "C" void kernel_launch(void* const* d_in, const int* in_sizes, int n_in,
                              void* d_out, int out_size)
{
    const float* x      = (const float*)d_in[0];
    const float* params = (const float*)d_in[1];
    float* out = (float*)d_out;
    (void)in_sizes; (void)n_in; (void)out_size;

    cudaFuncSetAttribute(condlane_mma_kernel,
                         cudaFuncAttributeMaxDynamicSharedMemorySize, SMEM_TOTAL);

    dim3 gx(LL / TP, 4);
    prep_x_kernel<<<gx, 256>>>(x);
    prep_w_kernel<<<NINST, 256>>>(params);

    dim3 grid(LL / TP, NINST);   // 320 x 32
    condlane_mma_kernel<<<grid, NTHR, SMEM_TOTAL>>>(params, out);
}